// round 2
// baseline (speedup 1.0000x reference)
#include <cuda_runtime.h>
#include <cstdint>

// ---------------------------------------------------------------------------
// DecoderRNNWithAttention — GB300 sm_103a
//
// Key simplifications (exact, not approximations):
//  * attention softmax is over a single "pixel" -> alpha == 1 -> context ==
//    features. The entire attention subnetwork (enc_W/dec_W/full_W) is dead.
//  * input projection X @ W_ih^T is precomputed for all 25 steps (one GEMM).
//  * vocab projection is batched over the 24 emitted steps (one big GEMM).
//
// Precision: tf32 mma.sync with rna rounding. GEMMs feeding the LSTM
// recurrence use a 3-term tf32 split (hi*hi + hi*lo + lo*hi) == ~fp32
// accuracy; the final vocab GEMM uses plain tf32 (~4e-4 rel err, one-shot).
// ---------------------------------------------------------------------------

constexpr int BB  = 128;          // batch
constexpr int TT  = 25;           // timesteps
constexpr int EE  = 512;          // embed dim
constexpr int HH  = 1024;         // hidden
constexpr int ENC = 400;          // encoder feature dim
constexpr int VOC = 32000;        // vocab
constexpr int KRAW = EE + ENC;    // 912
constexpr int KIN  = 928;         // 912 padded to mult of 32
constexpr int G4   = 4 * HH;      // 4096 gates
constexpr int MX   = TT * BB;     // 3200 rows of X / Gin
constexpr int MO   = (TT - 1) * BB; // 3072 rows of Hbuf

// ------------------------- scratch (static, no cudaMalloc) -----------------
__device__ float g_X[MX * KIN];            // 11.9 MB
__device__ float g_Wp[G4 * KIN];           // 15.2 MB padded W_ih
__device__ float g_bias[G4];               // b_ih + b_hh
__device__ float g_Gin[MX * G4];           // 52.4 MB input-proj gates
__device__ float g_gates[BB * G4];         // per-step gates
__device__ float g_h[BB * HH];
__device__ float g_c[BB * HH];
__device__ float g_Hb[MO * HH];            // 12.6 MB hidden states t=1..24

// ------------------------- helpers -----------------------------------------
__device__ __forceinline__ uint32_t f2tf(float x) {
    uint32_t u;
    asm("cvt.rna.tf32.f32 %0, %1;" : "=r"(u) : "f"(x));
    return u;
}

__device__ __forceinline__ void mma_tf32(float (&d)[4], const uint32_t (&a)[4],
                                         const uint32_t (&b)[2]) {
    asm volatile(
        "mma.sync.aligned.m16n8k8.row.col.f32.tf32.tf32.f32 "
        "{%0,%1,%2,%3},{%4,%5,%6,%7},{%8,%9},{%0,%1,%2,%3};"
        : "+f"(d[0]), "+f"(d[1]), "+f"(d[2]), "+f"(d[3])
        : "r"(a[0]), "r"(a[1]), "r"(a[2]), "r"(a[3]), "r"(b[0]), "r"(b[1]));
}

// ------------------------- generic NT tf32 GEMM -----------------------------
// C[M,N] = A[M,K] * B[N,K]^T  (both K-contiguous), K % BK == 0, exact tiling.
// SPLIT: 3-term tf32 split for ~fp32 accuracy.
// EPI 0: C = acc + bias[col]                      (row-major C, ld = N)
// EPI 1: C = acc + addend[row*N+col]              (row-major C, ld = N)
// EPI 2: out[(b*24 + t)*VOC + col] = acc + bias   (row = t*128 + b remap)
template <int BM, int BN, int BK, int WMS, int WNS, bool SPLIT, int EPI>
__global__ void __launch_bounds__(WMS * WNS * 32)
gemm_nt(const float* __restrict__ A, const float* __restrict__ Bw,
        const float* __restrict__ bias, const float* __restrict__ addend,
        float* __restrict__ C, int M, int N, int K) {
    constexpr int THREADS = WMS * WNS * 32;
    constexpr int MF = BM / (WMS * 16);
    constexpr int NF = BN / (WNS * 8);
    constexpr int LD = BK + 4;            // pad -> conflict-free frag loads
    constexpr int NSP = SPLIT ? 2 : 1;
    constexpr int KS = BK / 8;
    constexpr int AIT = (BM * (BK / 4)) / THREADS;
    constexpr int BIT = (BN * (BK / 4)) / THREADS;

    __shared__ uint32_t As[NSP][BM][LD];
    __shared__ uint32_t Bs[NSP][BN][LD];

    const int tid  = threadIdx.x;
    const int lane = tid & 31;
    const int warp = tid >> 5;
    const int wm = warp % WMS;
    const int wn = warp / WMS;
    const int gq = lane >> 2;   // group id (0..7)
    const int tq = lane & 3;    // thread-in-group
    const int m0 = blockIdx.y * BM;
    const int n0 = blockIdx.x * BN;

    float acc[MF][NF][4];
#pragma unroll
    for (int i = 0; i < MF; i++)
#pragma unroll
        for (int j = 0; j < NF; j++)
#pragma unroll
            for (int q = 0; q < 4; q++) acc[i][j][q] = 0.f;

    for (int kt = 0; kt < K; kt += BK) {
        // ---- load + tf32-round A tile ----
#pragma unroll
        for (int it = 0; it < AIT; it++) {
            int i = tid + it * THREADS;
            int r = i / (BK / 4);
            int c = (i % (BK / 4)) * 4;
            float4 v = *reinterpret_cast<const float4*>(
                &A[(size_t)(m0 + r) * K + kt + c]);
            float vv[4] = {v.x, v.y, v.z, v.w};
#pragma unroll
            for (int q = 0; q < 4; q++) {
                uint32_t hi = f2tf(vv[q]);
                As[0][r][c + q] = hi;
                if (SPLIT) As[1][r][c + q] = f2tf(vv[q] - __uint_as_float(hi));
            }
        }
        // ---- load + tf32-round B tile ----
#pragma unroll
        for (int it = 0; it < BIT; it++) {
            int i = tid + it * THREADS;
            int r = i / (BK / 4);
            int c = (i % (BK / 4)) * 4;
            float4 v = *reinterpret_cast<const float4*>(
                &Bw[(size_t)(n0 + r) * K + kt + c]);
            float vv[4] = {v.x, v.y, v.z, v.w};
#pragma unroll
            for (int q = 0; q < 4; q++) {
                uint32_t hi = f2tf(vv[q]);
                Bs[0][r][c + q] = hi;
                if (SPLIT) Bs[1][r][c + q] = f2tf(vv[q] - __uint_as_float(hi));
            }
        }
        __syncthreads();

#pragma unroll
        for (int ks = 0; ks < KS; ks++) {
            uint32_t af[NSP][MF][4];
            uint32_t bf[NSP][NF][2];
#pragma unroll
            for (int mi = 0; mi < MF; mi++) {
                int row = wm * (MF * 16) + mi * 16;
#pragma unroll
                for (int s = 0; s < NSP; s++) {
                    af[s][mi][0] = As[s][row + gq][ks * 8 + tq];
                    af[s][mi][1] = As[s][row + gq + 8][ks * 8 + tq];
                    af[s][mi][2] = As[s][row + gq][ks * 8 + tq + 4];
                    af[s][mi][3] = As[s][row + gq + 8][ks * 8 + tq + 4];
                }
            }
#pragma unroll
            for (int ni = 0; ni < NF; ni++) {
                int col = wn * (NF * 8) + ni * 8;
#pragma unroll
                for (int s = 0; s < NSP; s++) {
                    bf[s][ni][0] = Bs[s][col + gq][ks * 8 + tq];
                    bf[s][ni][1] = Bs[s][col + gq][ks * 8 + tq + 4];
                }
            }
#pragma unroll
            for (int mi = 0; mi < MF; mi++)
#pragma unroll
                for (int ni = 0; ni < NF; ni++) {
                    mma_tf32(acc[mi][ni], af[0][mi], bf[0][ni]);
                    if (SPLIT) {
                        mma_tf32(acc[mi][ni], af[0][mi], bf[1][ni]);
                        mma_tf32(acc[mi][ni], af[1][mi], bf[0][ni]);
                    }
                }
        }
        __syncthreads();
    }

    // ---- epilogue ----
#pragma unroll
    for (int mi = 0; mi < MF; mi++) {
#pragma unroll
        for (int ni = 0; ni < NF; ni++) {
            int row = m0 + wm * (MF * 16) + mi * 16 + gq;
            int col = n0 + wn * (NF * 8) + ni * 8 + tq * 2;
#pragma unroll
            for (int half = 0; half < 2; half++) {
                int r = row + half * 8;
                float v0 = acc[mi][ni][half * 2 + 0];
                float v1 = acc[mi][ni][half * 2 + 1];
                if constexpr (EPI == 0) {
                    v0 += bias[col];
                    v1 += bias[col + 1];
                    *reinterpret_cast<float2*>(&C[(size_t)r * N + col]) =
                        make_float2(v0, v1);
                } else if constexpr (EPI == 1) {
                    float2 ad = *reinterpret_cast<const float2*>(
                        &addend[(size_t)r * N + col]);
                    *reinterpret_cast<float2*>(&C[(size_t)r * N + col]) =
                        make_float2(v0 + ad.x, v1 + ad.y);
                } else {
                    int b  = r & (BB - 1);
                    int t  = r >> 7;
                    size_t o = ((size_t)b * (TT - 1) + t) * VOC + col;
                    v0 += bias[col];
                    v1 += bias[col + 1];
                    *reinterpret_cast<float2*>(&C[o]) = make_float2(v0, v1);
                }
            }
        }
    }
}

// ------------------------- small kernels ------------------------------------
__global__ void prep_bias_k(const float* __restrict__ bi,
                            const float* __restrict__ bh, float* out) {
    int i = blockIdx.x * blockDim.x + threadIdx.x;
    if (i < G4) out[i] = bi[i] + bh[i];
}

__global__ void prep_W_k(const float* __restrict__ W, float* __restrict__ Wp) {
    int i = blockIdx.x * blockDim.x + threadIdx.x;
    if (i >= G4 * KIN) return;
    int n = i / KIN, k = i % KIN;
    Wp[i] = (k < KRAW) ? W[(size_t)n * KRAW + k] : 0.f;
}

// X[t*128+b, :] = [ emb(t==0 ? <SOS>=1 : captions[b,t-1]) , features[b] , 0pad ]
__global__ void prep_X_k(const float* __restrict__ feat,
                         const int* __restrict__ caps,
                         const float* __restrict__ emb, float* __restrict__ X) {
    int i = blockIdx.x * blockDim.x + threadIdx.x;
    if (i >= MX * KIN) return;
    int r = i / KIN, k = i % KIN;
    int t = r / BB, b = r % BB;
    float v;
    if (k < EE) {
        int tok = (t == 0) ? 1 : caps[b * TT + (t - 1)];
        v = emb[(size_t)tok * EE + k];
    } else if (k < EE + ENC) {
        v = feat[b * ENC + (k - EE)];
    } else {
        v = 0.f;
    }
    X[i] = v;
}

__global__ void zero_hc_k(float* h, float* c) {
    int i = blockIdx.x * blockDim.x + threadIdx.x;
    if (i < BB * HH) { h[i] = 0.f; c[i] = 0.f; }
}

// gates layout: [i | f | g | o] blocks of HH columns (torch LSTMCell order)
__global__ void lstm_cell_k(const float* __restrict__ gates,
                            float* __restrict__ c, float* __restrict__ h,
                            float* __restrict__ hb, int t) {
    int i = blockIdx.x * blockDim.x + threadIdx.x;
    if (i >= BB * HH) return;
    int b = i >> 10, j = i & (HH - 1);
    const float* gr = gates + (size_t)b * G4;
    float gi = gr[j], gf = gr[HH + j], gg = gr[2 * HH + j], go = gr[3 * HH + j];
    float si = 1.f / (1.f + expf(-gi));
    float sf = 1.f / (1.f + expf(-gf));
    float so = 1.f / (1.f + expf(-go));
    float cn = sf * c[i] + si * tanhf(gg);
    float hn = so * tanhf(cn);
    c[i] = cn;
    h[i] = hn;
    if (t > 0) hb[(size_t)(t - 1) * BB * HH + i] = hn;  // emitted steps 1..24
}

// ------------------------- launch -------------------------------------------
extern "C" void kernel_launch(void* const* d_in, const int* in_sizes, int n_in,
                              void* d_out, int out_size) {
    const float* features = (const float*)d_in[0];
    const int*   captions = (const int*)d_in[1];
    const float* emb_W    = (const float*)d_in[2];
    const float* W_ih     = (const float*)d_in[3];
    const float* W_hh     = (const float*)d_in[4];
    const float* b_ih     = (const float*)d_in[5];
    const float* b_hh     = (const float*)d_in[6];
    // d_in[7..12]: attention weights — provably dead (softmax over 1 element)
    const float* fcn_W    = (const float*)d_in[13];
    const float* fcn_b    = (const float*)d_in[14];
    float* out = (float*)d_out;

    float *X, *Wp, *bias, *Gin, *gates, *h, *c, *Hb;
    cudaGetSymbolAddress((void**)&X, g_X);
    cudaGetSymbolAddress((void**)&Wp, g_Wp);
    cudaGetSymbolAddress((void**)&bias, g_bias);
    cudaGetSymbolAddress((void**)&Gin, g_Gin);
    cudaGetSymbolAddress((void**)&gates, g_gates);
    cudaGetSymbolAddress((void**)&h, g_h);
    cudaGetSymbolAddress((void**)&c, g_c);
    cudaGetSymbolAddress((void**)&Hb, g_Hb);

    // prep
    prep_bias_k<<<(G4 + 255) / 256, 256>>>(b_ih, b_hh, bias);
    prep_W_k<<<(G4 * KIN + 255) / 256, 256>>>(W_ih, Wp);
    prep_X_k<<<(MX * KIN + 255) / 256, 256>>>(features, captions, emb_W, X);
    zero_hc_k<<<(BB * HH + 255) / 256, 256>>>(h, c);

    // input projection for ALL timesteps: Gin = X @ W_ih^T + (b_ih+b_hh)
    gemm_nt<128, 128, 16, 2, 4, true, 0>
        <<<dim3(G4 / 128, MX / 128), 256>>>(X, Wp, bias, nullptr, Gin,
                                            MX, G4, KIN);

    // sequential LSTM: gates = Gin[t] + h @ W_hh^T ; elementwise cell update
    for (int t = 0; t < TT; t++) {
        gemm_nt<128, 32, 16, 4, 1, true, 1>
            <<<dim3(G4 / 32, 1), 128>>>(h, W_hh, nullptr,
                                        Gin + (size_t)t * BB * G4, gates,
                                        BB, G4, HH);
        lstm_cell_k<<<(BB * HH + 255) / 256, 256>>>(gates, c, h, Hb, t);
    }

    // batched vocab projection: out[b, t, :] = Hb[t*128+b] @ fcn_W^T + fcn_b
    gemm_nt<128, 128, 32, 2, 4, false, 2>
        <<<dim3(VOC / 128, MO / 128), 256>>>(Hb, fcn_W, fcn_b, nullptr, out,
                                             MO, VOC, HH);
}